// round 11
// baseline (speedup 1.0000x reference)
#include <cuda_runtime.h>
#include <stdint.h>

// Scratch: __device__ globals (no allocation allowed).
// Invariant: g_counts all-zero at entry (zero static init; k_penalty resets
// each slot after reading it -> graph-replay deterministic).
#define MAX_N 131072
__device__ int   g_counts[MAX_N];
__device__ float g_penalty[MAX_N];

// Valence table: default 4; {1:1, 6:4, 7:3, 8:2, 9:1, 15:5, 16:6, 17:7}
__device__ __forceinline__ float valence_of(int z) {
    switch (z) {
        case 1:  return 1.0f;
        case 9:  return 1.0f;
        case 7:  return 3.0f;
        case 8:  return 2.0f;
        case 15: return 5.0f;
        case 16: return 6.0f;
        case 17: return 7.0f;
        default: return 4.0f;   // covers 6 and all others
    }
}

// K1: scatter-add bond counts (int32 indices). TWO int4 loads issued up front
// (independent, MLP=2), then 8 back-to-back fire-and-forget REDs — doubles
// same-class LSU pipelining vs the 1-quad/4-RED loop that measured 23.6us at
// 0.46 RED/cyc/SM (issue=8.6%). Thread 0 zeroes the loss slot.
__global__ void k_count_edges(const int* __restrict__ row, int nq, int pairs,
                              int E, float* loss_slot) {
    if (blockIdx.x == 0 && threadIdx.x == 0) *loss_slot = 0.0f;
    int i = blockIdx.x * blockDim.x + threadIdx.x;
    if (i < pairs) {
        const int4* q = reinterpret_cast<const int4*>(row);
        int j = i + pairs;
        int4 a = q[i];                                  // both loads in flight
        int4 b = (j < nq) ? q[j] : make_int4(a.x, a.y, a.z, a.w);
        atomicAdd(&g_counts[a.x], 1);
        atomicAdd(&g_counts[a.y], 1);
        atomicAdd(&g_counts[a.z], 1);
        atomicAdd(&g_counts[a.w], 1);
        if (j < nq) {
            atomicAdd(&g_counts[b.x], 1);
            atomicAdd(&g_counts[b.y], 1);
            atomicAdd(&g_counts[b.z], 1);
            atomicAdd(&g_counts[b.w], 1);
        }
    }
    // tail: E % 4 edges (gather atom index from row[])
    if (blockIdx.x == 0 && threadIdx.x < (E & 3)) {
        atomicAdd(&g_counts[row[nq * 4 + threadIdx.x]], 1);
    }
}

// K2: per-atom penalty precompute + loss reduce + scratch self-clean.
// Tiny kernel (N threads over 1.2 MB of L2-resident data).
__global__ void k_penalty(const int* __restrict__ types, int n,
                          float loss_scale, float* loss_slot) {
    __shared__ float s_part[32];
    int i = blockIdx.x * blockDim.x + threadIdx.x;
    float viol = 0.0f;
    if (i < n) {
        viol = fmaxf((float)g_counts[i] - valence_of(types[i]), 0.0f);
        g_counts[i] = 0;   // reset for next graph replay
        g_penalty[i] = (viol > 0.0f) ? (1.0f - 0.1f * viol) : 1.0f;
    }
    // warp reduce
    #pragma unroll
    for (int off = 16; off > 0; off >>= 1)
        viol += __shfl_down_sync(0xFFFFFFFFu, viol, off);
    int lane = threadIdx.x & 31, warp = threadIdx.x >> 5;
    if (lane == 0) s_part[warp] = viol;
    __syncthreads();
    if (threadIdx.x == 0) {
        float s = 0.0f;
        int nw = blockDim.x >> 5;
        for (int w = 0; w < nw; w++) s += s_part[w];
        if (s != 0.0f) atomicAdd(loss_slot, s * loss_scale);
    }
}

// K3: h_new = h * penalty[row]. R3-measured shape (plain LDG/STG, precomputed
// penalty), 2 float4 per thread (neutral-to-positive in R10; kept).
__global__ void k_scale_h(const float4* __restrict__ h, float4* __restrict__ out,
                          int total4, int pairs, int d4, int shift) {
    int i0 = blockIdx.x * blockDim.x + threadIdx.x;
    if (i0 < pairs) {
        int i1 = i0 + pairs;
        int r0 = (shift >= 0) ? (i0 >> shift) : (i0 / d4);
        float4 a = h[i0];
        float p0 = g_penalty[r0];
        if (i1 < total4) {
            int r1 = (shift >= 0) ? (i1 >> shift) : (i1 / d4);
            float4 b = h[i1];
            float p1 = g_penalty[r1];
            a.x *= p0; a.y *= p0; a.z *= p0; a.w *= p0;
            b.x *= p1; b.y *= p1; b.z *= p1; b.w *= p1;
            out[i0] = a;
            out[i1] = b;
        } else {
            a.x *= p0; a.y *= p0; a.z *= p0; a.w *= p0;
            out[i0] = a;
        }
    }
}

extern "C" void kernel_launch(void* const* d_in, const int* in_sizes, int n_in,
                              void* d_out, int out_size) {
    const float* h     = (const float*)d_in[0];
    const int*   edges = (const int*)d_in[1];   // [2, E] int32; row = edges[0..E)
    const int*   types = (const int*)d_in[2];   // [N] int32
    float* out = (float*)d_out;

    const int N = in_sizes[2];
    const int E = in_sizes[1] / 2;
    const int D = in_sizes[0] / N;

    float* loss_slot = out + (out_size - 1);

    // K1: edge scatter (+ zero loss slot), 2 int4 / 8 REDs per thread
    {
        int nq = E / 4;
        int pairs = (nq + 1) / 2;
        int threads = 256;
        int blocks = (pairs + threads - 1) / threads;
        if (blocks < 1) blocks = 1;
        k_count_edges<<<blocks, threads>>>(edges, nq, pairs, E, loss_slot);
    }
    // K2: penalty precompute + loss + counts reset
    {
        float loss_scale = 0.05f / (float)N;
        int threads = 256, blocks = (N + threads - 1) / threads;
        k_penalty<<<blocks, threads>>>(types, N, loss_scale, loss_slot);
    }
    // K3: scale features (2 float4 per thread)
    {
        int d4 = D / 4;
        int shift = -1;
        if (d4 > 0 && (d4 & (d4 - 1)) == 0) {
            shift = 0;
            while ((1 << shift) != d4) shift++;
        }
        int total4 = (int)((long long)N * D / 4);
        int pairs = (total4 + 1) / 2;
        int threads = 256;
        int blocks = (pairs + threads - 1) / threads;
        if (blocks < 1) blocks = 1;
        k_scale_h<<<blocks, threads>>>((const float4*)h, (float4*)out,
                                       total4, pairs, d4, shift);
    }
}